// round 5
// baseline (speedup 1.0000x reference)
#include <cuda_runtime.h>

#define TT 1024
#define NT (TT*64)
#define NB 128
#define LN64 4.158883083359672f

// ---- device scratch (static only) ----
__device__ float g_u[NT], g_v[NT], g_emit[NT];
__device__ float g_bufA[NB * 4096];
__device__ float g_bufB[NB * 4096];
__device__ float g_sc[NB];
__device__ unsigned g_cnt[9];     // phase counters; self-resetting (zero at first launch)

// ============================================================
// Grid-wide spin barrier, phase p in [0,9). All NB blocks arrive.
// Last arriver resets slot (p-1 mod 9) -> safe across graph replays.
// ============================================================
__device__ __forceinline__ void gbar(int p, int tid)
{
    __syncthreads();
    if (tid == 0) {
        __threadfence();
        unsigned old = atomicAdd(&g_cnt[p], 1u);
        if (old == NB - 1u) {
            g_cnt[(p + 8) % 9] = 0u;
            __threadfence();
        }
        while (*((volatile unsigned*)&g_cnt[p]) < (unsigned)NB) { }
    }
    __syncthreads();
}

// ============================================================
// 64x64x64 GEMM, 256 threads: A padded (stride 65), B dense float4.
// ============================================================
__device__ __forceinline__ void gemm64_256(const float* __restrict__ Ap,
                                           const float* __restrict__ Bd,
                                           float acc[4][4], int tid)
{
    int tx = tid & 15, ty = tid >> 4;
    const float4* B4 = (const float4*)Bd;
    #pragma unroll
    for (int r = 0; r < 4; r++)
        #pragma unroll
        for (int c = 0; c < 4; c++) acc[r][c] = 0.f;
    #pragma unroll 4
    for (int m = 0; m < 64; m++) {
        float4 bv = B4[m * 16 + tx];
        #pragma unroll
        for (int r = 0; r < 4; r++) {
            float av = Ap[(ty * 4 + r) * 65 + m];
            acc[r][0] = fmaf(av, bv.x, acc[r][0]);
            acc[r][1] = fmaf(av, bv.y, acc[r][1]);
            acc[r][2] = fmaf(av, bv.z, acc[r][2]);
            acc[r][3] = fmaf(av, bv.w, acc[r][3]);
        }
    }
}

// ============================================================
// Column-split 64x64x NC GEMM with /64 rescale (tree levels).
// ============================================================
template <int NC>
__device__ __forceinline__ void tail_gemm(const float* __restrict__ Ag,
                                          const float* __restrict__ Bg,
                                          float* __restrict__ Cg, int col0,
                                          float* sA, float* sB, int tid)
{
    const float4* Ag4 = (const float4*)Ag;
    #pragma unroll
    for (int g = 0; g < 4; g++) {
        int p = tid + g * 256;
        float4 a = __ldcg(Ag4 + p);
        int j = p >> 4, m4 = (p & 15) << 2;
        sA[j * 65 + m4 + 0] = a.x;
        sA[j * 65 + m4 + 1] = a.y;
        sA[j * 65 + m4 + 2] = a.z;
        sA[j * 65 + m4 + 3] = a.w;
    }
    constexpr int NC4 = NC / 4;
    const float4* Bg4 = (const float4*)Bg;
    float4* sB4 = (float4*)sB;
    for (int q = tid; q < 64 * NC4; q += 256) {
        int m = q / NC4, c = q - m * NC4;
        sB4[q] = __ldcg(Bg4 + m * 16 + (col0 >> 2) + c);
    }
    __syncthreads();

    constexpr int R = NC4 / 4;     // rows per thread (2 for NC=32, 1 for NC=16)
    int tx = tid % NC4, ty = tid / NC4;
    float acc[R][4];
    #pragma unroll
    for (int r = 0; r < R; r++)
        #pragma unroll
        for (int c = 0; c < 4; c++) acc[r][c] = 0.f;

    #pragma unroll 4
    for (int m = 0; m < 64; m++) {
        float4 bv = sB4[m * NC4 + tx];
        #pragma unroll
        for (int r = 0; r < R; r++) {
            float av = sA[(ty * R + r) * 65 + m];
            acc[r][0] = fmaf(av, bv.x, acc[r][0]);
            acc[r][1] = fmaf(av, bv.y, acc[r][1]);
            acc[r][2] = fmaf(av, bv.z, acc[r][2]);
            acc[r][3] = fmaf(av, bv.w, acc[r][3]);
        }
    }
    const float inv = 1.f / 64.f;
    float4* Cg4 = (float4*)Cg;
    #pragma unroll
    for (int r = 0; r < R; r++)
        Cg4[(ty * R + r) * 16 + (col0 >> 2) + tx] =
            make_float4(acc[r][0]*inv, acc[r][1]*inv, acc[r][2]*inv, acc[r][3]*inv);
}

// ============================================================
// THE kernel: gather -> radix-8 leaf fold -> 7 tree levels -> logZ
// grid = 128 blocks x 256 threads (co-resident unconditionally)
// ============================================================
__global__ __launch_bounds__(256) void mono_kernel(
    const float* __restrict__ obs,  const int* __restrict__ cids,
    const float* __restrict__ emb,
    const float* __restrict__ ecw,  const float* __restrict__ ecb,
    const float* __restrict__ elw,  const float* __restrict__ elb,
    const float* __restrict__ tcw,  const float* __restrict__ tcb,
    const float* __restrict__ tlw,  const float* __restrict__ tlb,
    float* __restrict__ out)
{
    __shared__ __align__(16) float SM[8320];   // carved per phase (33.3 KB)
    __shared__ float u_s[64], v_s[64], em_s[64], e0_s[64];
    __shared__ float red[8];
    __shared__ float s_scalar;

    int tid  = threadIdx.x, b = blockIdx.x;
    int lane = tid & 31, w = tid >> 5;

    //================ P0: gather + folded prep ================
    {
        float* we0 = SM;
        float* we1 = SM + 256;
        float* wt0 = SM + 512;
        float* wt1 = SM + 768;
        int d = tid;
        float em1 = (d > 0)   ? elw[d-1] : 0.f;
        float e0v = elw[d];
        float ep1 = (d < 255) ? elw[d+1] : 0.f;
        we0[d] = ecw[0]*ep1 + ecw[1]*e0v + ecw[2]*em1;
        we1[d] = ecw[3]*ep1 + ecw[4]*e0v + ecw[5]*em1;
        float tm1 = (d > 0)   ? tlw[d-1] : 0.f;
        float t0v = tlw[d];
        float tp1 = (d < 255) ? tlw[d+1] : 0.f;
        wt0[d] = tcw[0]*tp1 + tcw[1]*t0v + tcw[2]*tm1;
        wt1[d] = tcw[3]*tp1 + tcw[4]*t0v + tcw[5]*tm1;

        float vs = e0v;
        #pragma unroll
        for (int o = 16; o; o >>= 1) vs += __shfl_xor_sync(0xffffffffu, vs, o);
        if (lane == 0) red[w] = vs;
        __syncthreads();
        if (tid == 0) {
            float s = 0.f;
            #pragma unroll
            for (int i = 0; i < 8; i++) s += red[i];
            s_scalar = ecb[0] * s + elb[0];
        }
        __syncthreads();
        float ce = s_scalar;

        int t = b * 8 + w;                      // one t per warp
        float od = 0.f;
        #pragma unroll
        for (int q = 0; q < 8; q++)
            od += obs[t * 256 + lane + q * 32] * we0[lane + q * 32];
        #pragma unroll
        for (int o = 16; o; o >>= 1) od += __shfl_xor_sync(0xffffffffu, od, o);

        const float4* A4 = (const float4*)we1;
        const float4* B4 = (const float4*)wt0;
        const float4* C4 = (const float4*)wt1;
        float4 a0 = A4[lane*2], a1 = A4[lane*2+1];
        float4 b0 = B4[lane*2], b1 = B4[lane*2+1];
        float4 c0 = C4[lane*2], c1 = C4[lane*2+1];

        for (int i = 0; i < 64; i += 4) {
            int r = t * 64 + i;
            int cid[4];
            #pragma unroll
            for (int j = 0; j < 4; j++) cid[j] = __ldg(cids + r + j);
            float4 x[4][2];
            #pragma unroll
            for (int j = 0; j < 4; j++) {
                const float4* e4 = (const float4*)(emb + (size_t)cid[j] * 256);
                x[j][0] = __ldg(e4 + lane * 2);
                x[j][1] = __ldg(e4 + lane * 2 + 1);
            }
            float de[4], du[4], dv[4];
            #pragma unroll
            for (int j = 0; j < 4; j++) {
                float4 p = x[j][0], q = x[j][1];
                de[j] = p.x*a0.x + p.y*a0.y + p.z*a0.z + p.w*a0.w
                      + q.x*a1.x + q.y*a1.y + q.z*a1.z + q.w*a1.w;
                du[j] = p.x*b0.x + p.y*b0.y + p.z*b0.z + p.w*b0.w
                      + q.x*b1.x + q.y*b1.y + q.z*b1.z + q.w*b1.w;
                dv[j] = p.x*c0.x + p.y*c0.y + p.z*c0.z + p.w*c0.w
                      + q.x*c1.x + q.y*c1.y + q.z*c1.z + q.w*c1.w;
            }
            #pragma unroll
            for (int j = 0; j < 4; j++) {
                #pragma unroll
                for (int o = 16; o; o >>= 1) {
                    de[j] += __shfl_xor_sync(0xffffffffu, de[j], o);
                    du[j] += __shfl_xor_sync(0xffffffffu, du[j], o);
                    dv[j] += __shfl_xor_sync(0xffffffffu, dv[j], o);
                }
            }
            #pragma unroll
            for (int j = 0; j < 4; j++) {
                if (lane == j) {
                    float xx = de[j] + od + ce;
                    g_emit[r + j] = __fdividef(1.f, 1.f + __expf(-xx));
                    g_u[r + j] = du[j];
                    g_v[r + j] = dv[j];
                }
            }
        }
    }
    gbar(0, tid);

    //================ P1: 8 leaves -> left-fold product ================
    {
        float tv = __ldg(tlw + tid);
        #pragma unroll
        for (int o = 16; o; o >>= 1) tv += __shfl_xor_sync(0xffffffffu, tv, o);
        if (lane == 0) red[w] = tv;
        __syncthreads();
        if (tid == 0) {
            float s = 0.f;
            #pragma unroll
            for (int i = 0; i < 8; i++) s += red[i];
            s_scalar = tcb[0] * s + tlb[0];
        }
        __syncthreads();
        float ct = s_scalar;

        float* Ppad = SM;          // 4160 floats, stride 65
        float* Mden = SM + 4160;   // 4096 floats, dense

        auto build = [&](int t, float* dst, int stride) {
            if (tid < 64) {
                u_s[tid]  = __ldcg(g_u + t * 64 + tid);
                v_s[tid]  = __ldcg(g_v + (t + 1) * 64 + tid);
                em_s[tid] = __ldcg(g_emit + (t + 1) * 64 + tid);
                e0_s[tid] = (t == 0) ? __ldcg(g_emit + tid) : 0.f;
            }
            __syncthreads();
            #pragma unroll
            for (int i = 0; i < 16; i++) {
                int idx = tid + i * 256;
                int j = idx >> 6, k = idx & 63;
                float xx = u_s[j] + v_s[k] + ct;
                float sg = __fdividef(1.f, 1.f + __expf(-xx));
                dst[j * stride + k] = __expf(sg + em_s[k] + e0_s[j]);
            }
            __syncthreads();
        };

        int t0 = 8 * b;
        build(t0, Ppad, 65);
        int tx = tid & 15, ty = tid >> 4;
        for (int s = 1; s < 8; s++) {
            int t = t0 + s;
            if (t >= TT - 1) break;          // identity tail (block 127)
            build(t, Mden, 64);
            float acc[4][4];
            gemm64_256(Ppad, Mden, acc, tid);
            __syncthreads();
            #pragma unroll
            for (int r = 0; r < 4; r++)
                #pragma unroll
                for (int c = 0; c < 4; c++)
                    Ppad[(ty * 4 + r) * 65 + tx * 4 + c] = acc[r][c];
            __syncthreads();
        }

        // block-max rescale -> g_bufB[b]
        float mx = 0.f;
        #pragma unroll
        for (int i = 0; i < 16; i++) {
            int idx = tid + i * 256;
            mx = fmaxf(mx, Ppad[(idx >> 6) * 65 + (idx & 63)]);
        }
        #pragma unroll
        for (int o = 16; o; o >>= 1) mx = fmaxf(mx, __shfl_xor_sync(0xffffffffu, mx, o));
        if (lane == 0) red[w] = mx;
        __syncthreads();
        if (tid == 0) {
            float m = red[0];
            #pragma unroll
            for (int i = 1; i < 8; i++) m = fmaxf(m, red[i]);
            s_scalar = m;
            g_sc[b] = logf(m);
        }
        __syncthreads();
        float inv = __fdividef(1.f, s_scalar);
        #pragma unroll
        for (int i = 0; i < 16; i++) {
            int idx = tid + i * 256;
            g_bufB[(size_t)b * 4096 + idx] =
                Ppad[(idx >> 6) * 65 + (idx & 63)] * inv;
        }
    }
    gbar(1, tid);

    float* sA = SM;
    float* sB = SM + 4160;

    // L2: 128 -> 64  (2 blocks/product, 32-col halves)   B -> A
    { int g = b >> 1, c0 = (b & 1) * 32;
      tail_gemm<32>(g_bufB + (size_t)(2*g)*4096, g_bufB + (size_t)(2*g+1)*4096,
                    g_bufA + (size_t)g*4096, c0, sA, sB, tid); }
    gbar(2, tid);
    // L3: 64 -> 32  (4 blocks/product, 16-col)           A -> B
    { int g = b >> 2, c0 = (b & 3) * 16;
      tail_gemm<16>(g_bufA + (size_t)(2*g)*4096, g_bufA + (size_t)(2*g+1)*4096,
                    g_bufB + (size_t)g*4096, c0, sA, sB, tid); }
    gbar(3, tid);
    // L4: 32 -> 16 (64 active)                            B -> A
    if (b < 64) { int g = b >> 2, c0 = (b & 3) * 16;
      tail_gemm<16>(g_bufB + (size_t)(2*g)*4096, g_bufB + (size_t)(2*g+1)*4096,
                    g_bufA + (size_t)g*4096, c0, sA, sB, tid); }
    gbar(4, tid);
    // L5: 16 -> 8 (32 active)                             A -> B
    if (b < 32) { int g = b >> 2, c0 = (b & 3) * 16;
      tail_gemm<16>(g_bufA + (size_t)(2*g)*4096, g_bufA + (size_t)(2*g+1)*4096,
                    g_bufB + (size_t)g*4096, c0, sA, sB, tid); }
    gbar(5, tid);
    // L6: 8 -> 4 (16 active)                              B -> A
    if (b < 16) { int g = b >> 2, c0 = (b & 3) * 16;
      tail_gemm<16>(g_bufB + (size_t)(2*g)*4096, g_bufB + (size_t)(2*g+1)*4096,
                    g_bufA + (size_t)g*4096, c0, sA, sB, tid); }
    gbar(6, tid);
    // L7: 4 -> 2 (8 active)                               A -> B
    if (b < 8) { int g = b >> 2, c0 = (b & 3) * 16;
      tail_gemm<16>(g_bufA + (size_t)(2*g)*4096, g_bufA + (size_t)(2*g+1)*4096,
                    g_bufB + (size_t)g*4096, c0, sA, sB, tid); }
    gbar(7, tid);
    // L8: 2 -> 1 (4 active)                               B -> A
    if (b < 4) { int c0 = b * 16;
      tail_gemm<16>(g_bufB, g_bufB + 4096, g_bufA, c0, sA, sB, tid); }
    gbar(8, tid);

    //================ final: logZ ================
    if (b == 0) {
        float s = 0.f;
        for (int i = tid; i < 4096; i += 256) s += __ldcg(g_bufA + i);
        #pragma unroll
        for (int o = 16; o; o >>= 1) s += __shfl_xor_sync(0xffffffffu, s, o);
        if (lane == 0) red[w] = s;
        __syncthreads();
        float sc = (tid < NB) ? __ldcg(g_sc + tid) : 0.f;
        #pragma unroll
        for (int o = 16; o; o >>= 1) sc += __shfl_xor_sync(0xffffffffu, sc, o);
        __shared__ float red2[8];
        if (lane == 0) red2[w] = sc;
        __syncthreads();
        if (tid == 0) {
            float tot = 0.f, scs = 0.f;
            #pragma unroll
            for (int i = 0; i < 8; i++) { tot += red[i]; scs += red2[i]; }
            out[0] = logf(tot) + scs + 127.f * LN64;
        }
    }
}

// ============================================================
extern "C" void kernel_launch(void* const* d_in, const int* in_sizes, int n_in,
                              void* d_out, int out_size)
{
    const float* obs = (const float*)d_in[0];
    const int*   cid = (const int*)  d_in[1];
    const float* emb = (const float*)d_in[2];
    const float* ecw = (const float*)d_in[3];
    const float* ecb = (const float*)d_in[4];
    const float* elw = (const float*)d_in[5];
    const float* elb = (const float*)d_in[6];
    const float* tcw = (const float*)d_in[7];
    const float* tcb = (const float*)d_in[8];
    const float* tlw = (const float*)d_in[9];
    const float* tlb = (const float*)d_in[10];
    float* out = (float*)d_out;

    mono_kernel<<<NB, 256>>>(obs, cid, emb, ecw, ecb, elw, elb,
                             tcw, tcb, tlw, tlb, out);
}

// round 6
// speedup vs baseline: 1.1920x; 1.1920x over previous
#include <cuda_runtime.h>

#define TT 1024
#define NB 128
#define ND 11              // poly degree 10 -> 11 terms, G is 11x11

// ---- device scratch (static only) ----
__device__ float g_Hm[NB][128];
__device__ float g_H2[16][128];
__device__ float g_L[ND], g_R[ND];
__device__ float g_sc[NB], g_sc2[16];
__device__ unsigned g_cnt[2];

// grid barrier: phase p in {0,1}; last arriver resets the other slot ->
// safe across graph replays (cnt starts 0, ends {0,NB}, other reset on entry)
__device__ __forceinline__ void gbar(int p, int tid)
{
    __threadfence();
    __syncthreads();
    if (tid == 0) {
        unsigned old = atomicAdd(&g_cnt[p], 1u);
        if (old == NB - 1u) {
            g_cnt[p ^ 1] = 0u;
            __threadfence();
        }
        while (*((volatile unsigned*)&g_cnt[p]) < (unsigned)NB) { }
    }
    __syncthreads();
}

__global__ __launch_bounds__(512) void mono_kernel(
    const float* __restrict__ obs,  const int* __restrict__ cids,
    const float* __restrict__ emb,
    const float* __restrict__ ecw,  const float* __restrict__ ecb,
    const float* __restrict__ elw,  const float* __restrict__ elb,
    const float* __restrict__ tcw,  const float* __restrict__ tcb,
    const float* __restrict__ tlw,  const float* __restrict__ tlb,
    float* __restrict__ out)
{
    __shared__ __align__(16) float we0[256], we1[256], wt0[256], wt1[256];
    __shared__ float u_s[9][64], v_s[9][64], ek_s[9][64];
    __shared__ float od_s[9];
    __shared__ float Bt[ND][ND];
    __shared__ float red[16];
    __shared__ float s_ce, s_ct, s_mx;
    __shared__ float UP[64][12], VP[64][12];
    __shared__ float Wt[ND][64];
    __shared__ float Gb[9][128];     // Gb[s] = G_{8b+s-1} (121 used, pad 128)
    __shared__ float Hp[2][128];
    __shared__ int   cid_s[576];

    int tid  = threadIdx.x, b = blockIdx.x;
    int lane = tid & 31, w = tid >> 5;

    //========== A: effective weights + scalar constants ==========
    if (tid < 256) {
        int d = tid;
        float em1 = (d > 0)   ? elw[d-1] : 0.f;
        float e0v = elw[d];
        float ep1 = (d < 255) ? elw[d+1] : 0.f;
        we0[d] = ecw[0]*ep1 + ecw[1]*e0v + ecw[2]*em1;
        we1[d] = ecw[3]*ep1 + ecw[4]*e0v + ecw[5]*em1;
        float tm1 = (d > 0)   ? tlw[d-1] : 0.f;
        float t0v = tlw[d];
        float tp1 = (d < 255) ? tlw[d+1] : 0.f;
        wt0[d] = tcw[0]*tp1 + tcw[1]*t0v + tcw[2]*tm1;
        wt1[d] = tcw[3]*tp1 + tcw[4]*t0v + tcw[5]*tm1;
        float ve = e0v, vt = t0v;
        #pragma unroll
        for (int o = 16; o; o >>= 1) {
            ve += __shfl_xor_sync(0xffffffffu, ve, o);
            vt += __shfl_xor_sync(0xffffffffu, vt, o);
        }
        if (lane == 0) { red[w] = ve; red[8 + w] = vt; }
    }
    __syncthreads();
    if (tid == 0) {
        float Se = 0.f, St = 0.f;
        #pragma unroll
        for (int i = 0; i < 8; i++) { Se += red[i]; St += red[8 + i]; }
        s_ce = ecb[0] * Se + elb[0];
        s_ct = tcb[0] * St + tlb[0];
    }
    __syncthreads();

    //========== B: Taylor coeffs of g(d)=exp(sigmoid(ct+d)), fp64 ==========
    // sigma' = s(1-s):  p[n+1] = (p[n] - sum p_i p_{n-i}) / (n+1)
    // g'     = g*s'  :  q[n+1] = (sum (i+1) p_{i+1} q_{n-i}) / (n+1)
    // Bt[m][l] = q[m+l] * C(m+l, m)   (0 if m+l > 10)
    if (tid == 0) {
        double p[12], q[12];
        double ct = (double)s_ct;
        p[0] = 1.0 / (1.0 + exp(-ct));
        for (int n = 0; n < 10; n++) {
            double acc = 0.0;
            for (int i = 0; i <= n; i++) acc += p[i] * p[n-i];
            p[n+1] = (p[n] - acc) / (double)(n + 1);
        }
        q[0] = exp(p[0]);
        for (int n = 0; n < 10; n++) {
            double acc = 0.0;
            for (int i = 0; i <= n; i++) acc += (double)(i+1) * p[i+1] * q[n-i];
            q[n+1] = acc / (double)(n + 1);
        }
        double C[ND][ND];
        for (int n = 0; n < ND; n++) {
            C[n][0] = 1.0; C[n][n] = 1.0;
            for (int m = 1; m < n; m++) C[n][m] = C[n-1][m-1] + C[n-1][m];
        }
        for (int m = 0; m < ND; m++)
            for (int l = 0; l < ND; l++)
                Bt[m][l] = (m + l <= 10) ? (float)(q[m+l] * C[m+l][m]) : 0.f;
    }

    //========== C: gather frames [f0+sLo, f0+sHi] ==========
    int f0  = 8 * b;
    int sLo = (b == 0)      ? 0 : 1;
    int sHi = (b == NB - 1) ? 7 : 8;
    int rbase0 = sLo * 64;
    int nrows  = (sHi - sLo + 1) * 64;

    // stage candidate ids (coalesced)
    for (int i = tid; i < nrows; i += 512)
        cid_s[i] = __ldg(cids + f0 * 64 + rbase0 + i);

    // obs dot per slot (one warp each)
    if (w >= sLo && w <= sHi) {
        const float* op = obs + (size_t)(f0 + w) * 256;
        float od = 0.f;
        #pragma unroll
        for (int q8 = 0; q8 < 8; q8++)
            od += op[lane + 32*q8] * we0[lane + 32*q8];
        #pragma unroll
        for (int o = 16; o; o >>= 1) od += __shfl_xor_sync(0xffffffffu, od, o);
        if (lane == 0) od_s[w] = od;
    }
    __syncthreads();

    {
        const float4* A4 = (const float4*)we1;
        const float4* B4 = (const float4*)wt0;
        const float4* C4 = (const float4*)wt1;
        float4 a0 = A4[lane*2], a1 = A4[lane*2+1];
        float4 b0 = B4[lane*2], b1 = B4[lane*2+1];
        float4 c0 = C4[lane*2], c1 = C4[lane*2+1];

        for (int base = w * 4; base < nrows; base += 64) {
            float4 x[4][2];
            #pragma unroll
            for (int j = 0; j < 4; j++) {
                const float4* e4 = (const float4*)(emb + (size_t)cid_s[base + j] * 256);
                x[j][0] = __ldg(e4 + lane*2);
                x[j][1] = __ldg(e4 + lane*2 + 1);
            }
            float de[4], du[4], dv[4];
            #pragma unroll
            for (int j = 0; j < 4; j++) {
                float4 p = x[j][0], q = x[j][1];
                de[j] = p.x*a0.x + p.y*a0.y + p.z*a0.z + p.w*a0.w
                      + q.x*a1.x + q.y*a1.y + q.z*a1.z + q.w*a1.w;
                du[j] = p.x*b0.x + p.y*b0.y + p.z*b0.z + p.w*b0.w
                      + q.x*b1.x + q.y*b1.y + q.z*b1.z + q.w*b1.w;
                dv[j] = p.x*c0.x + p.y*c0.y + p.z*c0.z + p.w*c0.w
                      + q.x*c1.x + q.y*c1.y + q.z*c1.z + q.w*c1.w;
            }
            #pragma unroll
            for (int j = 0; j < 4; j++) {
                #pragma unroll
                for (int o = 16; o; o >>= 1) {
                    de[j] += __shfl_xor_sync(0xffffffffu, de[j], o);
                    du[j] += __shfl_xor_sync(0xffffffffu, du[j], o);
                    dv[j] += __shfl_xor_sync(0xffffffffu, dv[j], o);
                }
            }
            if (lane < 4) {
                int rr = rbase0 + base + lane;
                int s = rr >> 6, r = rr & 63;
                u_s[s][r]  = du[lane];
                v_s[s][r]  = dv[lane];
                ek_s[s][r] = de[lane];     // raw emit dot, transformed below
            }
        }
    }
    __syncthreads();

    // ek = exp(sigmoid(de + obsdot + ce))   (the only per-row transcendentals)
    for (int i = tid; i < nrows; i += 512) {
        int rr = rbase0 + i, s = rr >> 6, r = rr & 63;
        float x  = ek_s[s][r] + od_s[s] + s_ce;
        float sg = __fdividef(1.f, 1.f + __expf(-x));
        ek_s[s][r] = __expf(sg);
    }
    __syncthreads();

    //========== D: per frame slot -> 11x11 G (or R vector) ==========
    for (int s = 1; s <= sHi; s++) {
        if (tid < 64) {
            float u = u_s[s][tid], pw = 1.f;
            UP[tid][0] = 1.f;
            #pragma unroll
            for (int l = 1; l <= 10; l++) { pw *= u; UP[tid][l] = pw; }
        } else if (tid < 128) {
            int k = tid - 64;
            float v = v_s[s][k], pw = 1.f;
            VP[k][0] = 1.f;
            #pragma unroll
            for (int l = 1; l <= 10; l++) { pw *= v; VP[k][l] = pw; }
        }
        __syncthreads();
        for (int e = tid; e < ND * 64; e += 512) {
            int m = e >> 6, k = e & 63;
            float acc = 0.f;
            #pragma unroll
            for (int l = 0; l < ND; l++) acc = fmaf(Bt[m][l], VP[k][l], acc);
            Wt[m][k] = acc * ek_s[s][k];
        }
        __syncthreads();
        bool isR = (b == NB - 1 && s == 7);     // frame 1023 -> right boundary
        if (!isR) {
            if (tid < 121) {
                int m = tid / 11, l = tid - m * 11;
                float acc = 0.f;
                #pragma unroll 8
                for (int k = 0; k < 64; k++) acc = fmaf(Wt[m][k], UP[k][l], acc);
                Gb[s][tid] = acc;
            }
        } else {
            if (tid < ND) {
                float acc = 0.f;
                for (int k = 0; k < 64; k++) acc += Wt[tid][k];
                g_R[tid] = acc;
            }
        }
        __syncthreads();
    }
    // left boundary (frame 0, block 0): L[m] = sum_j ek0[j] * u0[j]^m
    if (b == 0 && tid < ND) {
        float acc = 0.f;
        for (int j = 0; j < 64; j++) {
            float u = u_s[0][j], pw = 1.f;
            for (int i = 0; i < tid; i++) pw *= u;
            acc = fmaf(ek_s[0][j], pw, acc);
        }
        g_L[tid] = acc;
    }

    //========== E: fold this block's G chain (left-to-right) ==========
    int ng = (b == NB - 1) ? 6 : 8;
    if (tid < 128) Hp[0][tid] = Gb[1][tid];
    __syncthreads();
    int cur = 0;
    for (int s = 2; s <= ng; s++) {
        if (tid < 121) {
            int m = tid / 11, l = tid - m * 11;
            float acc = 0.f;
            #pragma unroll
            for (int i = 0; i < ND; i++)
                acc = fmaf(Hp[cur][m*11 + i], Gb[s][i*11 + l], acc);
            Hp[cur ^ 1][tid] = acc;
        }
        cur ^= 1;
        __syncthreads();
    }
    {   // max-abs rescale
        float vv = (tid < 121) ? fabsf(Hp[cur][tid]) : 0.f;
        #pragma unroll
        for (int o = 16; o; o >>= 1) vv = fmaxf(vv, __shfl_xor_sync(0xffffffffu, vv, o));
        if (lane == 0) red[w] = vv;
        __syncthreads();
        if (tid == 0) {
            float m = red[0];
            #pragma unroll
            for (int i = 1; i < 16; i++) m = fmaxf(m, red[i]);
            s_mx = m;
            g_sc[b] = logf(m);
        }
        __syncthreads();
        float inv = __fdividef(1.f, s_mx);
        if (tid < 121) g_Hm[b][tid] = Hp[cur][tid] * inv;
    }
    gbar(0, tid);

    //========== F: 16 blocks fold 8 H's each ==========
    if (b < 16) {
        if (tid < 121) Hp[0][tid] = __ldcg(&g_Hm[8*b][tid]);
        __syncthreads();
        int c2 = 0;
        for (int i = 1; i < 8; i++) {
            if (tid < 121) Gb[0][tid] = __ldcg(&g_Hm[8*b + i][tid]);
            __syncthreads();
            if (tid < 121) {
                int m = tid / 11, l = tid - m * 11;
                float acc = 0.f;
                #pragma unroll
                for (int q = 0; q < ND; q++)
                    acc = fmaf(Hp[c2][m*11 + q], Gb[0][q*11 + l], acc);
                Hp[c2 ^ 1][tid] = acc;
            }
            c2 ^= 1;
            __syncthreads();
        }
        float vv = (tid < 121) ? fabsf(Hp[c2][tid]) : 0.f;
        #pragma unroll
        for (int o = 16; o; o >>= 1) vv = fmaxf(vv, __shfl_xor_sync(0xffffffffu, vv, o));
        if (lane == 0) red[w] = vv;
        __syncthreads();
        if (tid == 0) {
            float m = red[0];
            #pragma unroll
            for (int i = 1; i < 16; i++) m = fmaxf(m, red[i]);
            s_mx = m;
            g_sc2[b] = logf(m);
        }
        __syncthreads();
        float inv = __fdividef(1.f, s_mx);
        if (tid < 121) g_H2[b][tid] = Hp[c2][tid] * inv;
    }
    gbar(1, tid);

    //========== G: block 0 folds 16, applies boundary vectors ==========
    if (b == 0) {
        if (tid < 121) Hp[0][tid] = __ldcg(&g_H2[0][tid]);
        __syncthreads();
        int c3 = 0;
        for (int i = 1; i < 16; i++) {
            if (tid < 121) Gb[0][tid] = __ldcg(&g_H2[i][tid]);
            __syncthreads();
            if (tid < 121) {
                int m = tid / 11, l = tid - m * 11;
                float acc = 0.f;
                #pragma unroll
                for (int q = 0; q < ND; q++)
                    acc = fmaf(Hp[c3][m*11 + q], Gb[0][q*11 + l], acc);
                Hp[c3 ^ 1][tid] = acc;
            }
            c3 ^= 1;
            __syncthreads();
        }
        // scale sums
        float sv = (tid < NB) ? __ldcg(g_sc + tid) : 0.f;
        #pragma unroll
        for (int o = 16; o; o >>= 1) sv += __shfl_xor_sync(0xffffffffu, sv, o);
        if (lane == 0) red[w] = sv;
        __syncthreads();
        if (tid == 0) {
            float tot = red[0] + red[1] + red[2] + red[3];
            for (int i = 0; i < 16; i++) tot += g_sc2[i];
            // z = L^T * M * R
            float y[ND];
            for (int m = 0; m < ND; m++) {
                float acc = 0.f;
                for (int l = 0; l < ND; l++)
                    acc = fmaf(Hp[c3][m*11 + l], g_R[l], acc);
                y[m] = acc;
            }
            float z = 0.f;
            for (int m = 0; m < ND; m++) z = fmaf(g_L[m], y[m], z);
            out[0] = logf(z) + tot;
        }
    }
}

// ============================================================
extern "C" void kernel_launch(void* const* d_in, const int* in_sizes, int n_in,
                              void* d_out, int out_size)
{
    const float* obs = (const float*)d_in[0];
    const int*   cid = (const int*)  d_in[1];
    const float* emb = (const float*)d_in[2];
    const float* ecw = (const float*)d_in[3];
    const float* ecb = (const float*)d_in[4];
    const float* elw = (const float*)d_in[5];
    const float* elb = (const float*)d_in[6];
    const float* tcw = (const float*)d_in[7];
    const float* tcb = (const float*)d_in[8];
    const float* tlw = (const float*)d_in[9];
    const float* tlb = (const float*)d_in[10];
    float* out = (float*)d_out;

    mono_kernel<<<NB, 512>>>(obs, cid, emb, ecw, ecb, elw, elb,
                             tcw, tcb, tlw, tlb, out);
}

// round 7
// speedup vs baseline: 1.3740x; 1.1527x over previous
#include <cuda_runtime.h>

#define TT 1024
#define NB 128
#define ND 11              // poly degree 10 -> 11 terms, G is 11x11
#define BARBIG 0x40000000u

// ---- device scratch (static only) ----
__device__ float g_Hm[NB][128];
__device__ float g_H2[16][128];
__device__ float g_L[ND], g_R[ND];
__device__ float g_sc[NB], g_sc2[16];
__device__ unsigned g_cnt[2];

// Race-free grid barrier, 2 slots. Last arriver resets the OTHER slot
// FIRST, then releases via sentinel. Spinners wait for the sentinel, so
// no block can increment the other slot before its reset. End state per
// replay: {0, BARBIG} -> next replay starts clean on slot 0.
__device__ __forceinline__ void gbar(int p, int tid)
{
    __threadfence();
    __syncthreads();
    if (tid == 0) {
        unsigned old = atomicAdd(&g_cnt[p], 1u);
        if (old == NB - 1u) {
            g_cnt[p ^ 1] = 0u;
            __threadfence();
            atomicExch(&g_cnt[p], BARBIG);
        } else {
            while (*((volatile unsigned*)&g_cnt[p]) < BARBIG) { }
        }
    }
    __syncthreads();
}

__global__ __launch_bounds__(512) void mono_kernel(
    const float* __restrict__ obs,  const int* __restrict__ cids,
    const float* __restrict__ emb,
    const float* __restrict__ ecw,  const float* __restrict__ ecb,
    const float* __restrict__ elw,  const float* __restrict__ elb,
    const float* __restrict__ tcw,  const float* __restrict__ tcb,
    const float* __restrict__ tlw,  const float* __restrict__ tlb,
    float* __restrict__ out)
{
    __shared__ __align__(16) float we0[256], we1[256], wt0[256], wt1[256];
    __shared__ float u_s[9][64], v_s[9][64], ek_s[9][64];
    __shared__ float od_s[9];
    __shared__ float Bt[ND][ND];
    __shared__ float red[16];
    __shared__ float s_ce, s_ct, s_mx;
    __shared__ float UP[64][12], VP[64][12];
    __shared__ float Wt[ND][64];
    __shared__ float Gb[9][128];
    __shared__ float Hp[2][128];
    __shared__ int   cid_s[576];

    int tid  = threadIdx.x, b = blockIdx.x;
    int lane = tid & 31, w = tid >> 5;

    //========== A: effective weights + scalar constants ==========
    if (tid < 256) {
        int d = tid;
        float em1 = (d > 0)   ? elw[d-1] : 0.f;
        float e0v = elw[d];
        float ep1 = (d < 255) ? elw[d+1] : 0.f;
        we0[d] = ecw[0]*ep1 + ecw[1]*e0v + ecw[2]*em1;
        we1[d] = ecw[3]*ep1 + ecw[4]*e0v + ecw[5]*em1;
        float tm1 = (d > 0)   ? tlw[d-1] : 0.f;
        float t0v = tlw[d];
        float tp1 = (d < 255) ? tlw[d+1] : 0.f;
        wt0[d] = tcw[0]*tp1 + tcw[1]*t0v + tcw[2]*tm1;
        wt1[d] = tcw[3]*tp1 + tcw[4]*t0v + tcw[5]*tm1;
        float ve = e0v, vt = t0v;
        #pragma unroll
        for (int o = 16; o; o >>= 1) {
            ve += __shfl_xor_sync(0xffffffffu, ve, o);
            vt += __shfl_xor_sync(0xffffffffu, vt, o);
        }
        if (lane == 0) { red[w] = ve; red[8 + w] = vt; }
    }
    __syncthreads();
    if (tid == 0) {
        float Se = 0.f, St = 0.f;
        #pragma unroll
        for (int i = 0; i < 8; i++) { Se += red[i]; St += red[8 + i]; }
        s_ce = ecb[0] * Se + elb[0];
        s_ct = tcb[0] * St + tlb[0];
    }
    __syncthreads();

    //========== B: Taylor coeffs of g(d)=exp(sigmoid(ct+d)), fp32 ==========
    if (tid == 0) {
        float p[12], q[12];
        float ct = s_ct;
        p[0] = 1.f / (1.f + expf(-ct));
        #pragma unroll
        for (int n = 0; n < 10; n++) {
            float acc = 0.f;
            for (int i = 0; i <= n; i++) acc += p[i] * p[n-i];
            p[n+1] = (p[n] - acc) / (float)(n + 1);
        }
        q[0] = expf(p[0]);
        #pragma unroll
        for (int n = 0; n < 10; n++) {
            float acc = 0.f;
            for (int i = 0; i <= n; i++) acc += (float)(i+1) * p[i+1] * q[n-i];
            q[n+1] = acc / (float)(n + 1);
        }
        float C[ND][ND];
        for (int n = 0; n < ND; n++) {
            C[n][0] = 1.f; C[n][n] = 1.f;
            for (int m = 1; m < n; m++) C[n][m] = C[n-1][m-1] + C[n-1][m];
        }
        for (int m = 0; m < ND; m++)
            for (int l = 0; l < ND; l++)
                Bt[m][l] = (m + l <= 10) ? q[m+l] * C[m+l][m] : 0.f;
    }

    //========== C: gather frames [f0+sLo, f0+sHi] ==========
    int f0  = 8 * b;
    int sLo = (b == 0)      ? 0 : 1;
    int sHi = (b == NB - 1) ? 7 : 8;
    int rbase0 = sLo * 64;
    int nrows  = (sHi - sLo + 1) * 64;

    for (int i = tid; i < nrows; i += 512)
        cid_s[i] = __ldg(cids + f0 * 64 + rbase0 + i);

    if (w >= sLo && w <= sHi) {
        const float* op = obs + (size_t)(f0 + w) * 256;
        float od = 0.f;
        #pragma unroll
        for (int q8 = 0; q8 < 8; q8++)
            od += op[lane + 32*q8] * we0[lane + 32*q8];
        #pragma unroll
        for (int o = 16; o; o >>= 1) od += __shfl_xor_sync(0xffffffffu, od, o);
        if (lane == 0) od_s[w] = od;
    }
    __syncthreads();

    {
        const float4* A4 = (const float4*)we1;
        const float4* B4 = (const float4*)wt0;
        const float4* C4 = (const float4*)wt1;
        float4 a0 = A4[lane*2], a1 = A4[lane*2+1];
        float4 b0 = B4[lane*2], b1 = B4[lane*2+1];
        float4 c0 = C4[lane*2], c1 = C4[lane*2+1];

        float4 X0[4][2], X1[4][2];

        auto loadg = [&](float4 (&X)[4][2], int bs) {
            #pragma unroll
            for (int j = 0; j < 4; j++) {
                const float4* e4 = (const float4*)(emb + (size_t)cid_s[bs + j] * 256);
                X[j][0] = __ldg(e4 + lane*2);
                X[j][1] = __ldg(e4 + lane*2 + 1);
            }
        };
        auto reduceg = [&](float4 (&X)[4][2], int bs) {
            float de[4], du[4], dv[4];
            #pragma unroll
            for (int j = 0; j < 4; j++) {
                float4 p = X[j][0], q = X[j][1];
                de[j] = p.x*a0.x + p.y*a0.y + p.z*a0.z + p.w*a0.w
                      + q.x*a1.x + q.y*a1.y + q.z*a1.z + q.w*a1.w;
                du[j] = p.x*b0.x + p.y*b0.y + p.z*b0.z + p.w*b0.w
                      + q.x*b1.x + q.y*b1.y + q.z*b1.z + q.w*b1.w;
                dv[j] = p.x*c0.x + p.y*c0.y + p.z*c0.z + p.w*c0.w
                      + q.x*c1.x + q.y*c1.y + q.z*c1.z + q.w*c1.w;
            }
            #pragma unroll
            for (int j = 0; j < 4; j++) {
                #pragma unroll
                for (int o = 16; o; o >>= 1) {
                    de[j] += __shfl_xor_sync(0xffffffffu, de[j], o);
                    du[j] += __shfl_xor_sync(0xffffffffu, du[j], o);
                    dv[j] += __shfl_xor_sync(0xffffffffu, dv[j], o);
                }
            }
            if (lane < 4) {
                int rr = rbase0 + bs + lane;
                int s = rr >> 6, r = rr & 63;
                u_s[s][r]  = du[lane];
                v_s[s][r]  = dv[lane];
                ek_s[s][r] = de[lane];
            }
        };

        // software-pipelined: prefetch next group before reducing current
        int base = w * 4;
        if (base < nrows) loadg(X0, base);
        while (base < nrows) {
            if (base + 64 < nrows) loadg(X1, base + 64);
            reduceg(X0, base);
            base += 64;
            if (base >= nrows) break;
            if (base + 64 < nrows) loadg(X0, base + 64);
            reduceg(X1, base);
            base += 64;
        }
    }
    __syncthreads();

    // ek = exp(sigmoid(de + obsdot + ce))
    for (int i = tid; i < nrows; i += 512) {
        int rr = rbase0 + i, s = rr >> 6, r = rr & 63;
        float x  = ek_s[s][r] + od_s[s] + s_ce;
        float sg = __fdividef(1.f, 1.f + __expf(-x));
        ek_s[s][r] = __expf(sg);
    }
    __syncthreads();

    //========== D: per frame slot -> 11x11 G (or R vector) ==========
    for (int s = 1; s <= sHi; s++) {
        if (tid < 64) {
            float u = u_s[s][tid], pw = 1.f;
            UP[tid][0] = 1.f;
            #pragma unroll
            for (int l = 1; l <= 10; l++) { pw *= u; UP[tid][l] = pw; }
        } else if (tid < 128) {
            int k = tid - 64;
            float v = v_s[s][k], pw = 1.f;
            VP[k][0] = 1.f;
            #pragma unroll
            for (int l = 1; l <= 10; l++) { pw *= v; VP[k][l] = pw; }
        }
        __syncthreads();
        for (int e = tid; e < ND * 64; e += 512) {
            int m = e >> 6, k = e & 63;
            float acc = 0.f;
            #pragma unroll
            for (int l = 0; l < ND; l++) acc = fmaf(Bt[m][l], VP[k][l], acc);
            Wt[m][k] = acc * ek_s[s][k];
        }
        __syncthreads();
        bool isR = (b == NB - 1 && s == 7);
        if (!isR) {
            if (tid < 121) {
                int m = tid / 11, l = tid - m * 11;
                float acc = 0.f;
                #pragma unroll 8
                for (int k = 0; k < 64; k++) acc = fmaf(Wt[m][k], UP[k][l], acc);
                Gb[s][tid] = acc;
            }
        } else {
            if (tid < ND) {
                float acc = 0.f;
                for (int k = 0; k < 64; k++) acc += Wt[tid][k];
                g_R[tid] = acc;
            }
        }
        __syncthreads();
    }
    if (b == 0 && tid < ND) {
        float acc = 0.f;
        for (int j = 0; j < 64; j++) {
            float u = u_s[0][j], pw = 1.f;
            for (int i = 0; i < tid; i++) pw *= u;
            acc = fmaf(ek_s[0][j], pw, acc);
        }
        g_L[tid] = acc;
    }

    //========== E: fold this block's G chain ==========
    int ng = (b == NB - 1) ? 6 : 8;
    if (tid < 128) Hp[0][tid] = Gb[1][tid];
    __syncthreads();
    int cur = 0;
    for (int s = 2; s <= ng; s++) {
        if (tid < 121) {
            int m = tid / 11, l = tid - m * 11;
            float acc = 0.f;
            #pragma unroll
            for (int i = 0; i < ND; i++)
                acc = fmaf(Hp[cur][m*11 + i], Gb[s][i*11 + l], acc);
            Hp[cur ^ 1][tid] = acc;
        }
        cur ^= 1;
        __syncthreads();
    }
    {
        float vv = (tid < 121) ? fabsf(Hp[cur][tid]) : 0.f;
        #pragma unroll
        for (int o = 16; o; o >>= 1) vv = fmaxf(vv, __shfl_xor_sync(0xffffffffu, vv, o));
        if (lane == 0) red[w] = vv;
        __syncthreads();
        if (tid == 0) {
            float m = red[0];
            #pragma unroll
            for (int i = 1; i < 16; i++) m = fmaxf(m, red[i]);
            s_mx = m;
            g_sc[b] = logf(m);
        }
        __syncthreads();
        float inv = __fdividef(1.f, s_mx);
        if (tid < 121) g_Hm[b][tid] = Hp[cur][tid] * inv;
    }
    gbar(0, tid);

    //========== F: 16 blocks fold 8 H's each ==========
    if (b < 16) {
        if (tid < 121) Hp[0][tid] = __ldcg(&g_Hm[8*b][tid]);
        __syncthreads();
        int c2 = 0;
        for (int i = 1; i < 8; i++) {
            if (tid < 121) Gb[0][tid] = __ldcg(&g_Hm[8*b + i][tid]);
            __syncthreads();
            if (tid < 121) {
                int m = tid / 11, l = tid - m * 11;
                float acc = 0.f;
                #pragma unroll
                for (int q = 0; q < ND; q++)
                    acc = fmaf(Hp[c2][m*11 + q], Gb[0][q*11 + l], acc);
                Hp[c2 ^ 1][tid] = acc;
            }
            c2 ^= 1;
            __syncthreads();
        }
        float vv = (tid < 121) ? fabsf(Hp[c2][tid]) : 0.f;
        #pragma unroll
        for (int o = 16; o; o >>= 1) vv = fmaxf(vv, __shfl_xor_sync(0xffffffffu, vv, o));
        if (lane == 0) red[w] = vv;
        __syncthreads();
        if (tid == 0) {
            float m = red[0];
            #pragma unroll
            for (int i = 1; i < 16; i++) m = fmaxf(m, red[i]);
            s_mx = m;
            g_sc2[b] = logf(m);
        }
        __syncthreads();
        float inv = __fdividef(1.f, s_mx);
        if (tid < 121) g_H2[b][tid] = Hp[c2][tid] * inv;
    }
    gbar(1, tid);

    //========== G: block 0 folds 16, applies boundary vectors ==========
    if (b == 0) {
        if (tid < 121) Hp[0][tid] = __ldcg(&g_H2[0][tid]);
        __syncthreads();
        int c3 = 0;
        for (int i = 1; i < 16; i++) {
            if (tid < 121) Gb[0][tid] = __ldcg(&g_H2[i][tid]);
            __syncthreads();
            if (tid < 121) {
                int m = tid / 11, l = tid - m * 11;
                float acc = 0.f;
                #pragma unroll
                for (int q = 0; q < ND; q++)
                    acc = fmaf(Hp[c3][m*11 + q], Gb[0][q*11 + l], acc);
                Hp[c3 ^ 1][tid] = acc;
            }
            c3 ^= 1;
            __syncthreads();
        }
        float sv = (tid < NB) ? __ldcg(g_sc + tid) : 0.f;
        #pragma unroll
        for (int o = 16; o; o >>= 1) sv += __shfl_xor_sync(0xffffffffu, sv, o);
        if (lane == 0) red[w] = sv;
        __syncthreads();
        if (tid == 0) {
            float tot = red[0] + red[1] + red[2] + red[3];
            for (int i = 0; i < 16; i++) tot += g_sc2[i];
            float y[ND];
            for (int m = 0; m < ND; m++) {
                float acc = 0.f;
                for (int l = 0; l < ND; l++)
                    acc = fmaf(Hp[c3][m*11 + l], g_R[l], acc);
                y[m] = acc;
            }
            float z = 0.f;
            for (int m = 0; m < ND; m++) z = fmaf(g_L[m], y[m], z);
            out[0] = logf(z) + tot;
        }
    }
}

// ============================================================
extern "C" void kernel_launch(void* const* d_in, const int* in_sizes, int n_in,
                              void* d_out, int out_size)
{
    const float* obs = (const float*)d_in[0];
    const int*   cid = (const int*)  d_in[1];
    const float* emb = (const float*)d_in[2];
    const float* ecw = (const float*)d_in[3];
    const float* ecb = (const float*)d_in[4];
    const float* elw = (const float*)d_in[5];
    const float* elb = (const float*)d_in[6];
    const float* tcw = (const float*)d_in[7];
    const float* tcb = (const float*)d_in[8];
    const float* tlw = (const float*)d_in[9];
    const float* tlb = (const float*)d_in[10];
    float* out = (float*)d_out;

    mono_kernel<<<NB, 512>>>(obs, cid, emb, ecw, ecb, elw, elb,
                             tcw, tcb, tlw, tlb, out);
}